// round 14
// baseline (speedup 1.0000x reference)
#include <cuda_runtime.h>
#include <cuda_fp16.h>
#include <cstdint>

#define N_NODES 50000
#define N_EDGES 800000
#define NFEAT   512
#define NHID    128
#define NCLASS  40
#define PN_SCALE 1.0f

// ---------------- scratch (static device globals; no allocation) ----------------
__device__ __half g_h1 [(size_t)N_NODES * NHID];   // gemm output, fp16
__device__ __half g_agg[(size_t)N_NODES * NHID];   // spmm output, fp16
__device__ __half g_x  [(size_t)N_NODES * NHID];   // residual activations, fp16
__device__ int   g_cnt    [N_NODES];
__device__ int   g_row_ptr[N_NODES + 1];
__device__ int   g_cursor [N_NODES];
__device__ int   g_bsum   [128];
__device__ int2  g_csr    [N_EDGES];               // packed (col, val-bits)
__device__ float g_stats3 [3][129];                // per-layer colsum[128] + sum(x^2)
// pre-converted transposed W (fp16), layout [n][K] k-contiguous
// bases: L0=0 (128*512), L1=65536, L2=81920, W_out(padded n=64)=98304 (64*128)
__device__ __half g_wt[106496];

// ---------------- PTX helpers ----------------
__device__ __forceinline__ uint32_t smem_u32(const void* p) {
    uint32_t a;
    asm("{ .reg .u64 t; cvta.to.shared.u64 t, %1; cvt.u32.u64 %0, t; }" : "=r"(a) : "l"(p));
    return a;
}
__device__ __forceinline__ void ldsm4(uint32_t* r, uint32_t addr) {
    asm volatile("ldmatrix.sync.aligned.m8n8.x4.shared.b16 {%0,%1,%2,%3}, [%4];"
                 : "=r"(r[0]), "=r"(r[1]), "=r"(r[2]), "=r"(r[3]) : "r"(addr));
}
__device__ __forceinline__ void mma_fp16(float* c, const uint32_t* a, const uint32_t* b) {
    asm volatile(
        "mma.sync.aligned.m16n8k16.row.col.f32.f16.f16.f32 "
        "{%0,%1,%2,%3}, {%4,%5,%6,%7}, {%8,%9}, {%0,%1,%2,%3};"
        : "+f"(c[0]), "+f"(c[1]), "+f"(c[2]), "+f"(c[3])
        : "r"(a[0]), "r"(a[1]), "r"(a[2]), "r"(a[3]), "r"(b[0]), "r"(b[1]));
}
__device__ __forceinline__ float4 h4_to_f4(uint2 r) {
    float2 a = __half22float2(*reinterpret_cast<__half2*>(&r.x));
    float2 b = __half22float2(*reinterpret_cast<__half2*>(&r.y));
    return make_float4(a.x, a.y, b.x, b.y);
}
__device__ __forceinline__ uint2 f4_to_h4(float4 v) {
    __half2 h01 = __floats2half2_rn(v.x, v.y);
    __half2 h23 = __floats2half2_rn(v.z, v.w);
    return make_uint2(*reinterpret_cast<uint32_t*>(&h01), *reinterpret_cast<uint32_t*>(&h23));
}

// ---------------- prep: W conversion (fp16, incl. padded W_out) + zeroing --------
__global__ void prep_kernel(const float* __restrict__ W0,
                            const float* __restrict__ W1,
                            const float* __restrict__ W2,
                            const float* __restrict__ Wout) {
    int idx = blockIdx.x * blockDim.x + threadIdx.x;
    if (idx < N_NODES) g_cnt[idx] = 0;
    if (idx < 3 * 129) (&g_stats3[0][0])[idx] = 0.f;
    if (idx < 98304) {
        const float* W; int K, base, local;
        if (idx < 65536)      { W = W0; K = 512; base = 0;     local = idx; }
        else if (idx < 81920) { W = W1; K = 128; base = 65536; local = idx - 65536; }
        else                  { W = W2; K = 128; base = 81920; local = idx - 81920; }
        int k = local >> 7, n = local & 127;
        g_wt[base + (size_t)n * K + k] = __float2half_rn(W[local]);
    } else if (idx < 106496) {
        int local = idx - 98304;          // [64][128]
        int n = local >> 7, k = local & 127;
        float v = (n < NCLASS) ? Wout[k * NCLASS + n] : 0.f;
        g_wt[98304 + (size_t)n * 128 + k] = __float2half_rn(v);
    }
}

// ---------------- fused GEMM via fp16 mma.sync, software-pipelined ---------------
// C[M,128](fp16) = f(A)[M,K] @ W[K,128].  mode bits: 1=PairNorm transform on A,
// 2=+residual from Xio, 4=write transformed A back to Xio.
// AHALF: 1 = A is fp16 (agg), 0 = A is fp32 (layer-0 input x). Xio always fp16.
#define LDA 40   // padded row length in halves (80B: conflict-free ldmatrix)

template <int AHALF>
__global__ void __launch_bounds__(256) gemm_fused_kernel(
    const void* __restrict__ Araw, const __half* __restrict__ W,
    __half* __restrict__ C, __half* __restrict__ Xio,
    const float* __restrict__ stats,
    int M, int K, int mode) {
    __shared__ __half sA[128 * LDA];
    __shared__ __half sB[128 * LDA];
    __shared__ float s_mu[128];
    __shared__ float s_inv;

    const float*  Af = (const float*)Araw;
    const __half* Ah = (const __half*)Araw;

    int tid = threadIdx.x, lane = tid & 31, wid = tid >> 5;
    int wm = wid >> 2, wn = wid & 3;
    int m0 = blockIdx.x * 128;

    float inv = 0.f;
    if (mode & 1) {
        if (tid < 128) s_mu[tid] = stats[tid] * (1.f / (float)N_NODES);
        __syncthreads();
        if (tid == 0) {
            float musq = 0.f;
            #pragma unroll 8
            for (int j = 0; j < 128; j++) musq += s_mu[j] * s_mu[j];
            float var = (stats[128] - (float)N_NODES * musq) * (1.f / (float)N_NODES);
            s_inv = PN_SCALE * rsqrtf(1e-6f + var);
        }
        __syncthreads();
        inv = s_inv;
    }

    float acc[4][4][4];
    #pragma unroll
    for (int i = 0; i < 4; i++)
        #pragma unroll
        for (int j = 0; j < 4; j++)
            #pragma unroll
            for (int r = 0; r < 4; r++) acc[i][j][r] = 0.f;

    int mat = lane >> 3, rr = lane & 7;
    uint32_t aA = smem_u32(sA) + ((uint32_t)(wm * 64 + (mat & 1) * 8 + rr) * LDA + (mat >> 1) * 8) * 2;
    uint32_t aB = smem_u32(sB) + ((uint32_t)(wn * 32 + (mat >> 1) * 8 + rr) * LDA + (mat & 1) * 8) * 2;

    int sm_ = tid >> 3, sc4 = tid & 7;
    int sn = tid >> 2, sseg = tid & 3;

    float4 pa[4], pxo[4];
    uint4 pb[2];

    int nchunk = K >> 5;
    const bool dotrans = (mode & 1), dores = (mode & 2), dowrite = (mode & 4);

    {
        #pragma unroll
        for (int i = 0; i < 4; i++) {
            int m = sm_ + i * 32, gr = m0 + m;
            if (gr < M) {
                if (AHALF) pa[i] = h4_to_f4(*reinterpret_cast<const uint2*>(Ah + (size_t)gr * K + sc4 * 4));
                else       pa[i] = *reinterpret_cast<const float4*>(Af + (size_t)gr * K + sc4 * 4);
            } else pa[i] = make_float4(0.f, 0.f, 0.f, 0.f);
            if (dores)
                pxo[i] = (gr < M) ? h4_to_f4(*reinterpret_cast<const uint2*>(Xio + (size_t)gr * 128 + sc4 * 4))
                                  : make_float4(0.f, 0.f, 0.f, 0.f);
        }
        #pragma unroll
        for (int i = 0; i < 2; i++) {
            int n = sn + i * 64;
            pb[i] = *reinterpret_cast<const uint4*>(W + (size_t)n * K + sseg * 8);
        }
    }

    for (int c = 0; c < nchunk; c++) {
        int kc = c * 32;
        #pragma unroll
        for (int i = 0; i < 4; i++) {
            int m = sm_ + i * 32, gr = m0 + m;
            float4 v = pa[i];
            if (dotrans) {
                int cb = kc + sc4 * 4;
                v.x = fmaxf((v.x - s_mu[cb + 0]) * inv, 0.f);
                v.y = fmaxf((v.y - s_mu[cb + 1]) * inv, 0.f);
                v.z = fmaxf((v.z - s_mu[cb + 2]) * inv, 0.f);
                v.w = fmaxf((v.w - s_mu[cb + 3]) * inv, 0.f);
                if (dores) {
                    v.x += pxo[i].x; v.y += pxo[i].y; v.z += pxo[i].z; v.w += pxo[i].w;
                }
                if (dowrite && gr < M)
                    *reinterpret_cast<uint2*>(Xio + (size_t)gr * 128 + kc + sc4 * 4) = f4_to_h4(v);
            }
            uint2 hv = f4_to_h4(v);
            uint32_t off = (uint32_t)m * LDA + sc4 * 4;
            *reinterpret_cast<uint2*>(&sA[off]) = hv;
        }
        #pragma unroll
        for (int i = 0; i < 2; i++) {
            int n = sn + i * 64;
            uint32_t off = (uint32_t)n * LDA + sseg * 8;
            *reinterpret_cast<uint4*>(&sB[off]) = pb[i];
        }
        __syncthreads();

        if (c + 1 < nchunk) {
            int kn = kc + 32;
            #pragma unroll
            for (int i = 0; i < 4; i++) {
                int m = sm_ + i * 32, gr = m0 + m;
                if (gr < M) {
                    if (AHALF) pa[i] = h4_to_f4(*reinterpret_cast<const uint2*>(Ah + (size_t)gr * K + kn + sc4 * 4));
                    else       pa[i] = *reinterpret_cast<const float4*>(Af + (size_t)gr * K + kn + sc4 * 4);
                } else pa[i] = make_float4(0.f, 0.f, 0.f, 0.f);
                if (dores)
                    pxo[i] = (gr < M) ? h4_to_f4(*reinterpret_cast<const uint2*>(Xio + (size_t)gr * 128 + kn + sc4 * 4))
                                      : make_float4(0.f, 0.f, 0.f, 0.f);
            }
            #pragma unroll
            for (int i = 0; i < 2; i++) {
                int n = sn + i * 64;
                pb[i] = *reinterpret_cast<const uint4*>(W + (size_t)n * K + kn + sseg * 8);
            }
        }

        #pragma unroll
        for (int ks = 0; ks < 2; ks++) {
            uint32_t ko = ks * 32;
            uint32_t a4[4][4], b4[4][2];
            #pragma unroll
            for (int mt = 0; mt < 4; mt++) ldsm4(a4[mt], aA + mt * (16 * LDA * 2) + ko);
            #pragma unroll
            for (int p = 0; p < 2; p++)  ldsm4(&b4[p * 2][0], aB + p * (16 * LDA * 2) + ko);
            #pragma unroll
            for (int mt = 0; mt < 4; mt++)
                #pragma unroll
                for (int nt = 0; nt < 4; nt++) mma_fp16(acc[mt][nt], a4[mt], b4[nt]);
        }
        __syncthreads();
    }

    int mg = lane >> 2, cg = (lane & 3) * 2;
    #pragma unroll
    for (int mt = 0; mt < 4; mt++) {
        int r0 = m0 + wm * 64 + mt * 16 + mg;
        #pragma unroll
        for (int nt = 0; nt < 4; nt++) {
            int col = wn * 32 + nt * 8 + cg;
            if (r0 < M)
                *reinterpret_cast<__half2*>(C + (size_t)r0 * 128 + col) =
                    __floats2half2_rn(acc[mt][nt][0], acc[mt][nt][1]);
            if (r0 + 8 < M)
                *reinterpret_cast<__half2*>(C + (size_t)(r0 + 8) * 128 + col) =
                    __floats2half2_rn(acc[mt][nt][2], acc[mt][nt][3]);
        }
    }
}

// ---------------- head GEMM via fp16 mma.sync: C[M,40](fp16) ---------------------
// A = agg (fp16), Xio = residual (fp16). N padded to 64. CTA 128x64.
__global__ void __launch_bounds__(256) gemm_out_mma_kernel(
    const __half* __restrict__ A, const __half* __restrict__ W,
    const __half* __restrict__ Xio, const float* __restrict__ stats,
    __half* __restrict__ C, int M) {
    __shared__ __half sA[128 * LDA];
    __shared__ __half sB[64 * LDA];
    __shared__ float s_mu[128];
    __shared__ float s_inv;

    int tid = threadIdx.x, lane = tid & 31, wid = tid >> 5;
    int wm = wid >> 1, wn = wid & 1;
    int m0 = blockIdx.x * 128;

    if (tid < 128) s_mu[tid] = stats[tid] * (1.f / (float)N_NODES);
    __syncthreads();
    if (tid == 0) {
        float musq = 0.f;
        #pragma unroll 8
        for (int j = 0; j < 128; j++) musq += s_mu[j] * s_mu[j];
        float var = (stats[128] - (float)N_NODES * musq) * (1.f / (float)N_NODES);
        s_inv = PN_SCALE * rsqrtf(1e-6f + var);
    }
    __syncthreads();
    float inv = s_inv;

    float acc[2][4][4];
    #pragma unroll
    for (int i = 0; i < 2; i++)
        #pragma unroll
        for (int j = 0; j < 4; j++)
            #pragma unroll
            for (int r = 0; r < 4; r++) acc[i][j][r] = 0.f;

    int mat = lane >> 3, rr = lane & 7;
    uint32_t aA = smem_u32(sA) + ((uint32_t)(wm * 32 + (mat & 1) * 8 + rr) * LDA + (mat >> 1) * 8) * 2;
    uint32_t aB = smem_u32(sB) + ((uint32_t)(wn * 32 + (mat >> 1) * 8 + rr) * LDA + (mat & 1) * 8) * 2;

    int sm_ = tid >> 3, sc4 = tid & 7;
    int sn = tid >> 2, sseg = tid & 3;

    float4 pa[4], pxo[4];
    uint4 pb;

    {
        #pragma unroll
        for (int i = 0; i < 4; i++) {
            int m = sm_ + i * 32, gr = m0 + m;
            pa[i]  = (gr < M) ? h4_to_f4(*reinterpret_cast<const uint2*>(A   + (size_t)gr * 128 + sc4 * 4))
                              : make_float4(0.f, 0.f, 0.f, 0.f);
            pxo[i] = (gr < M) ? h4_to_f4(*reinterpret_cast<const uint2*>(Xio + (size_t)gr * 128 + sc4 * 4))
                              : make_float4(0.f, 0.f, 0.f, 0.f);
        }
        pb = *reinterpret_cast<const uint4*>(W + (size_t)sn * 128 + sseg * 8);
    }

    for (int c = 0; c < 4; c++) {
        int kc = c * 32;
        #pragma unroll
        for (int i = 0; i < 4; i++) {
            int m = sm_ + i * 32;
            float4 v = pa[i];
            int cb = kc + sc4 * 4;
            v.x = fmaxf((v.x - s_mu[cb + 0]) * inv, 0.f) + pxo[i].x;
            v.y = fmaxf((v.y - s_mu[cb + 1]) * inv, 0.f) + pxo[i].y;
            v.z = fmaxf((v.z - s_mu[cb + 2]) * inv, 0.f) + pxo[i].z;
            v.w = fmaxf((v.w - s_mu[cb + 3]) * inv, 0.f) + pxo[i].w;
            uint32_t off = (uint32_t)m * LDA + sc4 * 4;
            *reinterpret_cast<uint2*>(&sA[off]) = f4_to_h4(v);
        }
        {
            uint32_t off = (uint32_t)sn * LDA + sseg * 8;
            *reinterpret_cast<uint4*>(&sB[off]) = pb;
        }
        __syncthreads();

        if (c + 1 < 4) {
            int kn = kc + 32;
            #pragma unroll
            for (int i = 0; i < 4; i++) {
                int m = sm_ + i * 32, gr = m0 + m;
                pa[i]  = (gr < M) ? h4_to_f4(*reinterpret_cast<const uint2*>(A   + (size_t)gr * 128 + kn + sc4 * 4))
                                  : make_float4(0.f, 0.f, 0.f, 0.f);
                pxo[i] = (gr < M) ? h4_to_f4(*reinterpret_cast<const uint2*>(Xio + (size_t)gr * 128 + kn + sc4 * 4))
                                  : make_float4(0.f, 0.f, 0.f, 0.f);
            }
            pb = *reinterpret_cast<const uint4*>(W + (size_t)sn * 128 + kn + sseg * 8);
        }

        #pragma unroll
        for (int ks = 0; ks < 2; ks++) {
            uint32_t ko = ks * 32;
            uint32_t a4[2][4], b4[4][2];
            #pragma unroll
            for (int mt = 0; mt < 2; mt++) ldsm4(a4[mt], aA + mt * (16 * LDA * 2) + ko);
            #pragma unroll
            for (int p = 0; p < 2; p++)  ldsm4(&b4[p * 2][0], aB + p * (16 * LDA * 2) + ko);
            #pragma unroll
            for (int mt = 0; mt < 2; mt++)
                #pragma unroll
                for (int nt = 0; nt < 4; nt++) mma_fp16(acc[mt][nt], a4[mt], b4[nt]);
        }
        __syncthreads();
    }

    int mg = lane >> 2, cg = (lane & 3) * 2;
    #pragma unroll
    for (int mt = 0; mt < 2; mt++) {
        int r0 = m0 + wm * 32 + mt * 16 + mg;
        #pragma unroll
        for (int nt = 0; nt < 4; nt++) {
            int col = wn * 32 + nt * 8 + cg;
            if (col < NCLASS) {
                if (r0 < M)
                    *reinterpret_cast<__half2*>(C + (size_t)r0 * 40 + col) =
                        __floats2half2_rn(acc[mt][nt][0], acc[mt][nt][1]);
                if (r0 + 8 < M)
                    *reinterpret_cast<__half2*>(C + (size_t)(r0 + 8) * 40 + col) =
                        __floats2half2_rn(acc[mt][nt][2], acc[mt][nt][3]);
            }
        }
    }
}

// ---------------- CSR build ----------------
__global__ void hist_kernel(const int* __restrict__ erow) {
    int e = blockIdx.x * blockDim.x + threadIdx.x;
    if (e < N_EDGES) atomicAdd(&g_cnt[erow[e]], 1);
}
__global__ void scan1_kernel() {
    __shared__ int s[512];
    int tid = threadIdx.x;
    int i = blockIdx.x * 512 + tid;
    int v = (i < N_NODES) ? g_cnt[i] : 0;
    s[tid] = v;
    __syncthreads();
    #pragma unroll
    for (int off = 1; off < 512; off <<= 1) {
        int t = (tid >= off) ? s[tid - off] : 0;
        __syncthreads();
        s[tid] += t;
        __syncthreads();
    }
    if (i < N_NODES) g_row_ptr[i] = s[tid] - v;
    if (tid == 511) g_bsum[blockIdx.x] = s[511];
}
__global__ void scan23_kernel(int nb) {
    __shared__ int s[128];
    int tid = threadIdx.x;
    if (tid < 128) s[tid] = (tid < nb) ? g_bsum[tid] : 0;
    __syncthreads();
    #pragma unroll
    for (int off = 1; off < 128; off <<= 1) {
        int t = (tid < 128 && tid >= off) ? s[tid - off] : 0;
        __syncthreads();
        if (tid < 128) s[tid] += t;
        __syncthreads();
    }
    int base = s[blockIdx.x] - g_bsum[blockIdx.x];
    int i = blockIdx.x * 512 + tid;
    if (i < N_NODES) {
        int v = g_row_ptr[i] + base;
        g_row_ptr[i] = v;
        g_cursor[i]  = v;
    }
    if (i == 0) g_row_ptr[N_NODES] = N_EDGES;
}
__global__ void scatter_kernel(const int* __restrict__ erow,
                               const int* __restrict__ ecol,
                               const float* __restrict__ evalv) {
    int e = blockIdx.x * blockDim.x + threadIdx.x;
    if (e < N_EDGES) {
        int r = erow[e];
        int pos = atomicAdd(&g_cursor[r], 1);
        g_csr[pos] = make_int2(ecol[e], __float_as_int(evalv[e]));
    }
}

// ---------------- SpMM (F=128, fp16 gather, unroll 8) + fused PairNorm stats -----
// out is fp16 (agg); stats computed from fp32 accumulators pre-quantization.
__global__ void __launch_bounds__(256) spmm128_stats_kernel(
    const __half* __restrict__ h, __half* __restrict__ out, float* __restrict__ stats) {
    __shared__ float s_col[128];
    __shared__ float s_ss;
    int tid = threadIdx.x;
    if (tid < 128) s_col[tid] = 0.f;
    if (tid == 0) s_ss = 0.f;
    __syncthreads();

    int row  = (blockIdx.x * 256 + tid) >> 5;
    int lane = tid & 31;
    int s = g_row_ptr[row], e = g_row_ptr[row + 1];
    float4 acc = make_float4(0.f, 0.f, 0.f, 0.f);
    int i = s;
    for (; i + 8 <= e; i += 8) {
        int2 cv[8]; uint2 rr[8];
        #pragma unroll
        for (int u = 0; u < 8; u++) cv[u] = g_csr[i + u];
        #pragma unroll
        for (int u = 0; u < 8; u++)
            rr[u] = *reinterpret_cast<const uint2*>(h + (size_t)cv[u].x * 128 + lane * 4);
        #pragma unroll
        for (int u = 0; u < 8; u++) {
            float v = __int_as_float(cv[u].y);
            float2 a = __half22float2(*reinterpret_cast<__half2*>(&rr[u].x));
            float2 b = __half22float2(*reinterpret_cast<__half2*>(&rr[u].y));
            acc.x += v * a.x; acc.y += v * a.y; acc.z += v * b.x; acc.w += v * b.y;
        }
    }
    for (; i + 4 <= e; i += 4) {
        int2 cv[4]; uint2 rr[4];
        #pragma unroll
        for (int u = 0; u < 4; u++) cv[u] = g_csr[i + u];
        #pragma unroll
        for (int u = 0; u < 4; u++)
            rr[u] = *reinterpret_cast<const uint2*>(h + (size_t)cv[u].x * 128 + lane * 4);
        #pragma unroll
        for (int u = 0; u < 4; u++) {
            float v = __int_as_float(cv[u].y);
            float2 a = __half22float2(*reinterpret_cast<__half2*>(&rr[u].x));
            float2 b = __half22float2(*reinterpret_cast<__half2*>(&rr[u].y));
            acc.x += v * a.x; acc.y += v * a.y; acc.z += v * b.x; acc.w += v * b.y;
        }
    }
    for (; i < e; i++) {
        int2 cv = g_csr[i];
        float v = __int_as_float(cv.y);
        uint2 r = *reinterpret_cast<const uint2*>(h + (size_t)cv.x * 128 + lane * 4);
        float2 a = __half22float2(*reinterpret_cast<__half2*>(&r.x));
        float2 b = __half22float2(*reinterpret_cast<__half2*>(&r.y));
        acc.x += v * a.x; acc.y += v * a.y; acc.z += v * b.x; acc.w += v * b.y;
    }
    *reinterpret_cast<uint2*>(out + (size_t)row * 128 + lane * 4) = f4_to_h4(acc);

    atomicAdd(&s_col[lane * 4 + 0], acc.x);
    atomicAdd(&s_col[lane * 4 + 1], acc.y);
    atomicAdd(&s_col[lane * 4 + 2], acc.z);
    atomicAdd(&s_col[lane * 4 + 3], acc.w);
    float ss = acc.x * acc.x + acc.y * acc.y + acc.z * acc.z + acc.w * acc.w;
    #pragma unroll
    for (int o = 16; o > 0; o >>= 1) ss += __shfl_xor_sync(0xFFFFFFFFu, ss, o);
    if (lane == 0) atomicAdd(&s_ss, ss);
    __syncthreads();
    if (tid < 128) atomicAdd(&stats[tid], s_col[tid]);
    if (tid == 128) atomicAdd(&stats[128], s_ss);
}

// ---------------- SpMM final (F=40 fp16, half-warp per row) + bias -> d_out ------
__global__ void spmm40_kernel(const __half* __restrict__ h,
                              const float* __restrict__ b_out,
                              float* __restrict__ out) {
    int hw = (blockIdx.x * blockDim.x + threadIdx.x) >> 4;
    if (hw >= N_NODES) return;
    int l = threadIdx.x & 15;
    if (l >= 10) return;
    float4 acc = *reinterpret_cast<const float4*>(b_out + l * 4);
    int s = g_row_ptr[hw], e = g_row_ptr[hw + 1];
    int i = s;
    for (; i + 4 <= e; i += 4) {
        int2 cv[4]; uint2 rr[4];
        #pragma unroll
        for (int u = 0; u < 4; u++) cv[u] = g_csr[i + u];
        #pragma unroll
        for (int u = 0; u < 4; u++)
            rr[u] = *reinterpret_cast<const uint2*>(h + (size_t)cv[u].x * 40 + l * 4);
        #pragma unroll
        for (int u = 0; u < 4; u++) {
            float v = __int_as_float(cv[u].y);
            float2 a = __half22float2(*reinterpret_cast<__half2*>(&rr[u].x));
            float2 b = __half22float2(*reinterpret_cast<__half2*>(&rr[u].y));
            acc.x += v * a.x; acc.y += v * a.y; acc.z += v * b.x; acc.w += v * b.y;
        }
    }
    for (; i < e; i++) {
        int2 cv = g_csr[i];
        float v = __int_as_float(cv.y);
        uint2 r = *reinterpret_cast<const uint2*>(h + (size_t)cv.x * 40 + l * 4);
        float2 a = __half22float2(*reinterpret_cast<__half2*>(&r.x));
        float2 b = __half22float2(*reinterpret_cast<__half2*>(&r.y));
        acc.x += v * a.x; acc.y += v * a.y; acc.z += v * b.x; acc.w += v * b.y;
    }
    *reinterpret_cast<float4*>(out + (size_t)hw * 40 + l * 4) = acc;
}

// ---------------- driver ----------------
extern "C" void kernel_launch(void* const* d_in, const int* in_sizes, int n_in,
                              void* d_out, int out_size) {
    const float* x      = (const float*)d_in[0];
    const int*   erow   = (const int*)  d_in[1];
    const int*   ecol   = (const int*)  d_in[2];
    const float* evalv  = (const float*)d_in[3];
    const float* W0     = (const float*)d_in[4];
    const float* W1     = (const float*)d_in[6];
    const float* W2     = (const float*)d_in[8];
    const float* W_out  = (const float*)d_in[10];
    const float* b_out  = (const float*)d_in[11];
    float* out = (float*)d_out;

    __half* h1  = nullptr; cudaGetSymbolAddress((void**)&h1,  g_h1);
    __half* agg = nullptr; cudaGetSymbolAddress((void**)&agg, g_agg);
    __half* xb  = nullptr; cudaGetSymbolAddress((void**)&xb,  g_x);
    float*  st  = nullptr; cudaGetSymbolAddress((void**)&st,  g_stats3);
    __half* wt  = nullptr; cudaGetSymbolAddress((void**)&wt,  g_wt);

    const int NB_SCAN = (N_NODES + 511) / 512;      // 98
    const int EB      = (N_EDGES + 255) / 256;
    const int MB      = (N_NODES + 127) / 128;
    const int SPMM_B  = (N_NODES * 32) / 256;       // 6250

    // prep (W convert fp16 + zero) + CSR build
    prep_kernel<<<416, 256>>>(W0, W1, W2, W_out);
    hist_kernel<<<EB, 256>>>(erow);
    scan1_kernel<<<NB_SCAN, 512>>>();
    scan23_kernel<<<NB_SCAN, 512>>>(NB_SCAN);
    scatter_kernel<<<EB, 256>>>(erow, ecol, evalv);

    // layer 0: h = x @ W0 (A fp32)
    gemm_fused_kernel<0><<<MB, 256>>>(x, wt, h1, nullptr, nullptr, N_NODES, NFEAT, 0);
    spmm128_stats_kernel<<<SPMM_B, 256>>>(h1, agg, st);

    // layer 1 (A = agg fp16)
    gemm_fused_kernel<1><<<MB, 256>>>(agg, wt + 65536, h1, xb, st, N_NODES, NHID, 1 | 4);
    spmm128_stats_kernel<<<SPMM_B, 256>>>(h1, agg, st + 129);

    // layer 2
    gemm_fused_kernel<1><<<MB, 256>>>(agg, wt + 81920, h1, xb, st + 129, N_NODES, NHID, 1 | 2 | 4);
    spmm128_stats_kernel<<<SPMM_B, 256>>>(h1, agg, st + 258);

    // head: fp16 tensor-core GEMM (N padded to 64), then spmm + bias
    gemm_out_mma_kernel<<<MB, 256>>>(agg, wt + 98304, xb, st + 258, h1, N_NODES);
    spmm40_kernel<<<(N_NODES * 16 + 255) / 256, 256>>>(h1, b_out, out);
}

// round 17
// speedup vs baseline: 1.1436x; 1.1436x over previous
#include <cuda_runtime.h>
#include <cuda_fp16.h>
#include <cstdint>

#define N_NODES 50000
#define N_EDGES 800000
#define NFEAT   512
#define NHID    128
#define NCLASS  40
#define PN_SCALE 1.0f
#define MB_GRID 391   // (N_NODES + 127) / 128

// ---------------- scratch (static device globals; zero-initialized) --------------
__device__ __half g_h1 [(size_t)N_NODES * NHID];   // gemm output, fp16
__device__ float g_agg[(size_t)N_NODES * NHID];    // spmm output, fp32
__device__ float g_x  [(size_t)N_NODES * NHID];    // residual activations, fp32
__device__ int   g_cnt    [N_NODES];               // zeroed by scan23 each run
__device__ int   g_row_ptr[N_NODES + 1];
__device__ int   g_cursor [N_NODES];
__device__ int   g_bsum   [128];
__device__ int2  g_csr    [N_EDGES];               // packed (col, val-bits)
__device__ float g_stats3 [3][129];                // zeroed by later spmm each run
// pre-converted transposed W (fp16), layout [n][K] k-contiguous
// bases: L0=0 (128*512), L1=65536, L2=81920, W_out(padded n=64)=98304 (64*128)
__device__ __half g_wt[106496];

// ---------------- PTX helpers ----------------
__device__ __forceinline__ uint32_t smem_u32(const void* p) {
    uint32_t a;
    asm("{ .reg .u64 t; cvta.to.shared.u64 t, %1; cvt.u32.u64 %0, t; }" : "=r"(a) : "l"(p));
    return a;
}
__device__ __forceinline__ void ldsm4(uint32_t* r, uint32_t addr) {
    asm volatile("ldmatrix.sync.aligned.m8n8.x4.shared.b16 {%0,%1,%2,%3}, [%4];"
                 : "=r"(r[0]), "=r"(r[1]), "=r"(r[2]), "=r"(r[3]) : "r"(addr));
}
__device__ __forceinline__ void mma_fp16(float* c, const uint32_t* a, const uint32_t* b) {
    asm volatile(
        "mma.sync.aligned.m16n8k16.row.col.f32.f16.f16.f32 "
        "{%0,%1,%2,%3}, {%4,%5,%6,%7}, {%8,%9}, {%0,%1,%2,%3};"
        : "+f"(c[0]), "+f"(c[1]), "+f"(c[2]), "+f"(c[3])
        : "r"(a[0]), "r"(a[1]), "r"(a[2]), "r"(a[3]), "r"(b[0]), "r"(b[1]));
}

// ---------------- merged prep (W convert) + edge histogram -----------------------
// g_cnt arrives zeroed (static init on run 1; scan23 re-zeroes at each run).
__global__ void prep_hist_kernel(const float* __restrict__ W0,
                                 const float* __restrict__ W1,
                                 const float* __restrict__ W2,
                                 const float* __restrict__ Wout,
                                 const int* __restrict__ erow) {
    int idx = blockIdx.x * blockDim.x + threadIdx.x;
    if (idx < 98304) {
        const float* W; int K, base, local;
        if (idx < 65536)      { W = W0; K = 512; base = 0;     local = idx; }
        else if (idx < 81920) { W = W1; K = 128; base = 65536; local = idx - 65536; }
        else                  { W = W2; K = 128; base = 81920; local = idx - 81920; }
        int k = local >> 7, n = local & 127;
        g_wt[base + (size_t)n * K + k] = __float2half_rn(W[local]);
    } else if (idx < 106496) {
        int local = idx - 98304;          // [64][128]
        int n = local >> 7, k = local & 127;
        float v = (n < NCLASS) ? Wout[k * NCLASS + n] : 0.f;
        g_wt[98304 + (size_t)n * 128 + k] = __float2half_rn(v);
    }
    if (idx < N_EDGES) atomicAdd(&g_cnt[erow[idx]], 1);
}

// ---------------- fused GEMM body (fp16 mma.sync, software-pipelined) ------------
// C[M,128](fp16) = f(A)[M,K] @ W[K,128].  mode bits: 1=PairNorm transform on A,
// 2=+residual from Xio, 4=write transformed A back to Xio.
#define LDA 40   // padded row length in halves (80B: conflict-free ldmatrix)

__device__ __forceinline__ void gemm_fused_body(
    const float* __restrict__ A, const __half* __restrict__ W,
    __half* __restrict__ C, float* __restrict__ Xio,
    const float* __restrict__ stats,
    int M, int K, int mode, int bid) {
    __shared__ __align__(16) __half sA[128 * LDA];
    __shared__ __align__(16) __half sB[128 * LDA];
    __shared__ float s_mu[128];
    __shared__ float s_inv;

    int tid = threadIdx.x, lane = tid & 31, wid = tid >> 5;
    int wm = wid >> 2, wn = wid & 3;
    int m0 = bid * 128;

    float inv = 0.f;
    if (mode & 1) {
        if (tid < 128) s_mu[tid] = stats[tid] * (1.f / (float)N_NODES);
        __syncthreads();
        if (tid == 0) {
            float musq = 0.f;
            #pragma unroll 8
            for (int j = 0; j < 128; j++) musq += s_mu[j] * s_mu[j];
            float var = (stats[128] - (float)N_NODES * musq) * (1.f / (float)N_NODES);
            s_inv = PN_SCALE * rsqrtf(1e-6f + var);
        }
        __syncthreads();
        inv = s_inv;
    }

    float acc[4][4][4];
    #pragma unroll
    for (int i = 0; i < 4; i++)
        #pragma unroll
        for (int j = 0; j < 4; j++)
            #pragma unroll
            for (int r = 0; r < 4; r++) acc[i][j][r] = 0.f;

    int mat = lane >> 3, rr = lane & 7;
    uint32_t aA = smem_u32(sA) + ((uint32_t)(wm * 64 + (mat & 1) * 8 + rr) * LDA + (mat >> 1) * 8) * 2;
    uint32_t aB = smem_u32(sB) + ((uint32_t)(wn * 32 + (mat >> 1) * 8 + rr) * LDA + (mat & 1) * 8) * 2;

    int sm_ = tid >> 3, sc4 = tid & 7;
    int sn = tid >> 2, sseg = tid & 3;

    float4 pa[4], pxo[4];
    uint4 pb[2];

    int nchunk = K >> 5;
    const bool dotrans = (mode & 1), dores = (mode & 2), dowrite = (mode & 4);

    {
        #pragma unroll
        for (int i = 0; i < 4; i++) {
            int m = sm_ + i * 32, gr = m0 + m;
            pa[i] = (gr < M) ? *reinterpret_cast<const float4*>(A + (size_t)gr * K + sc4 * 4)
                             : make_float4(0.f, 0.f, 0.f, 0.f);
            if (dores)
                pxo[i] = (gr < M) ? *reinterpret_cast<const float4*>(Xio + (size_t)gr * 128 + sc4 * 4)
                                  : make_float4(0.f, 0.f, 0.f, 0.f);
        }
        #pragma unroll
        for (int i = 0; i < 2; i++) {
            int n = sn + i * 64;
            pb[i] = *reinterpret_cast<const uint4*>(W + (size_t)n * K + sseg * 8);
        }
    }

    for (int c = 0; c < nchunk; c++) {
        int kc = c * 32;
        #pragma unroll
        for (int i = 0; i < 4; i++) {
            int m = sm_ + i * 32, gr = m0 + m;
            float4 v = pa[i];
            if (dotrans) {
                int cb = kc + sc4 * 4;
                v.x = fmaxf((v.x - s_mu[cb + 0]) * inv, 0.f);
                v.y = fmaxf((v.y - s_mu[cb + 1]) * inv, 0.f);
                v.z = fmaxf((v.z - s_mu[cb + 2]) * inv, 0.f);
                v.w = fmaxf((v.w - s_mu[cb + 3]) * inv, 0.f);
                if (dores) {
                    v.x += pxo[i].x; v.y += pxo[i].y; v.z += pxo[i].z; v.w += pxo[i].w;
                }
                if (dowrite && gr < M)
                    *reinterpret_cast<float4*>(Xio + (size_t)gr * 128 + kc + sc4 * 4) = v;
            }
            __half2 h01 = __floats2half2_rn(v.x, v.y);
            __half2 h23 = __floats2half2_rn(v.z, v.w);
            uint32_t off = (uint32_t)m * LDA + sc4 * 4;
            *reinterpret_cast<uint2*>(&sA[off]) =
                make_uint2(*reinterpret_cast<uint32_t*>(&h01), *reinterpret_cast<uint32_t*>(&h23));
        }
        #pragma unroll
        for (int i = 0; i < 2; i++) {
            int n = sn + i * 64;
            uint32_t off = (uint32_t)n * LDA + sseg * 8;
            *reinterpret_cast<uint4*>(&sB[off]) = pb[i];
        }
        __syncthreads();

        if (c + 1 < nchunk) {
            int kn = kc + 32;
            #pragma unroll
            for (int i = 0; i < 4; i++) {
                int m = sm_ + i * 32, gr = m0 + m;
                pa[i] = (gr < M) ? *reinterpret_cast<const float4*>(A + (size_t)gr * K + kn + sc4 * 4)
                                 : make_float4(0.f, 0.f, 0.f, 0.f);
                if (dores)
                    pxo[i] = (gr < M) ? *reinterpret_cast<const float4*>(Xio + (size_t)gr * 128 + kn + sc4 * 4)
                                      : make_float4(0.f, 0.f, 0.f, 0.f);
            }
            #pragma unroll
            for (int i = 0; i < 2; i++) {
                int n = sn + i * 64;
                pb[i] = *reinterpret_cast<const uint4*>(W + (size_t)n * K + kn + sseg * 8);
            }
        }

        #pragma unroll
        for (int ks = 0; ks < 2; ks++) {
            uint32_t ko = ks * 32;
            uint32_t a4[4][4], b4[4][2];
            #pragma unroll
            for (int mt = 0; mt < 4; mt++) ldsm4(a4[mt], aA + mt * (16 * LDA * 2) + ko);
            #pragma unroll
            for (int p = 0; p < 2; p++)  ldsm4(&b4[p * 2][0], aB + p * (16 * LDA * 2) + ko);
            #pragma unroll
            for (int mt = 0; mt < 4; mt++)
                #pragma unroll
                for (int nt = 0; nt < 4; nt++) mma_fp16(acc[mt][nt], a4[mt], b4[nt]);
        }
        __syncthreads();
    }

    int mg = lane >> 2, cg = (lane & 3) * 2;
    #pragma unroll
    for (int mt = 0; mt < 4; mt++) {
        int r0 = m0 + wm * 64 + mt * 16 + mg;
        #pragma unroll
        for (int nt = 0; nt < 4; nt++) {
            int col = wn * 32 + nt * 8 + cg;
            if (r0 < M)
                *reinterpret_cast<__half2*>(C + (size_t)r0 * 128 + col) =
                    __floats2half2_rn(acc[mt][nt][0], acc[mt][nt][1]);
            if (r0 + 8 < M)
                *reinterpret_cast<__half2*>(C + (size_t)(r0 + 8) * 128 + col) =
                    __floats2half2_rn(acc[mt][nt][2], acc[mt][nt][3]);
        }
    }
}

__global__ void __launch_bounds__(256) gemm_fused_kernel(
    const float* __restrict__ A, const __half* __restrict__ W,
    __half* __restrict__ C, float* __restrict__ Xio,
    const float* __restrict__ stats, int M, int K, int mode) {
    gemm_fused_body(A, W, C, Xio, stats, M, K, mode, blockIdx.x);
}

// ---------------- fat kernel: layer-0 GEMM (blocks 0..MB-1) ∥ CSR scatter --------
__global__ void __launch_bounds__(256) gemm0_scatter_kernel(
    const float* __restrict__ A, const __half* __restrict__ W, __half* __restrict__ C,
    const int* __restrict__ erow, const int* __restrict__ ecol,
    const float* __restrict__ evalv) {
    if (blockIdx.x < MB_GRID) {
        gemm_fused_body(A, W, C, nullptr, nullptr, N_NODES, NFEAT, 0, blockIdx.x);
    } else {
        int e = (blockIdx.x - MB_GRID) * 256 + threadIdx.x;
        if (e < N_EDGES) {
            int r = erow[e];
            int pos = atomicAdd(&g_cursor[r], 1);
            g_csr[pos] = make_int2(ecol[e], __float_as_int(evalv[e]));
        }
    }
}

// ---------------- head GEMM via fp16 mma.sync: C[M,40](fp16) ---------------------
// N padded to 64. CTA 128x64, 8 warps = 4m x 2n of 32x32 warp tiles.
__global__ void __launch_bounds__(256) gemm_out_mma_kernel(
    const float* __restrict__ A, const __half* __restrict__ W,
    const float* __restrict__ Xio, const float* __restrict__ stats,
    __half* __restrict__ C, int M) {
    __shared__ __align__(16) __half sA[128 * LDA];
    __shared__ __align__(16) __half sB[64 * LDA];
    __shared__ float s_mu[128];
    __shared__ float s_inv;

    int tid = threadIdx.x, lane = tid & 31, wid = tid >> 5;
    int wm = wid >> 1, wn = wid & 1;
    int m0 = blockIdx.x * 128;

    if (tid < 128) s_mu[tid] = stats[tid] * (1.f / (float)N_NODES);
    __syncthreads();
    if (tid == 0) {
        float musq = 0.f;
        #pragma unroll 8
        for (int j = 0; j < 128; j++) musq += s_mu[j] * s_mu[j];
        float var = (stats[128] - (float)N_NODES * musq) * (1.f / (float)N_NODES);
        s_inv = PN_SCALE * rsqrtf(1e-6f + var);
    }
    __syncthreads();
    float inv = s_inv;

    float acc[2][4][4];
    #pragma unroll
    for (int i = 0; i < 2; i++)
        #pragma unroll
        for (int j = 0; j < 4; j++)
            #pragma unroll
            for (int r = 0; r < 4; r++) acc[i][j][r] = 0.f;

    int mat = lane >> 3, rr = lane & 7;
    uint32_t aA = smem_u32(sA) + ((uint32_t)(wm * 32 + (mat & 1) * 8 + rr) * LDA + (mat >> 1) * 8) * 2;
    uint32_t aB = smem_u32(sB) + ((uint32_t)(wn * 32 + (mat >> 1) * 8 + rr) * LDA + (mat & 1) * 8) * 2;

    int sm_ = tid >> 3, sc4 = tid & 7;
    int sn = tid >> 2, sseg = tid & 3;

    float4 pa[4], pxo[4];
    uint4 pb;

    {
        #pragma unroll
        for (int i = 0; i < 4; i++) {
            int m = sm_ + i * 32, gr = m0 + m;
            pa[i]  = (gr < M) ? *reinterpret_cast<const float4*>(A   + (size_t)gr * 128 + sc4 * 4)
                              : make_float4(0.f, 0.f, 0.f, 0.f);
            pxo[i] = (gr < M) ? *reinterpret_cast<const float4*>(Xio + (size_t)gr * 128 + sc4 * 4)
                              : make_float4(0.f, 0.f, 0.f, 0.f);
        }
        pb = *reinterpret_cast<const uint4*>(W + (size_t)sn * 128 + sseg * 8);
    }

    for (int c = 0; c < 4; c++) {
        int kc = c * 32;
        #pragma unroll
        for (int i = 0; i < 4; i++) {
            int m = sm_ + i * 32;
            float4 v = pa[i];
            int cb = kc + sc4 * 4;
            v.x = fmaxf((v.x - s_mu[cb + 0]) * inv, 0.f) + pxo[i].x;
            v.y = fmaxf((v.y - s_mu[cb + 1]) * inv, 0.f) + pxo[i].y;
            v.z = fmaxf((v.z - s_mu[cb + 2]) * inv, 0.f) + pxo[i].z;
            v.w = fmaxf((v.w - s_mu[cb + 3]) * inv, 0.f) + pxo[i].w;
            __half2 h01 = __floats2half2_rn(v.x, v.y);
            __half2 h23 = __floats2half2_rn(v.z, v.w);
            uint32_t off = (uint32_t)m * LDA + sc4 * 4;
            *reinterpret_cast<uint2*>(&sA[off]) =
                make_uint2(*reinterpret_cast<uint32_t*>(&h01), *reinterpret_cast<uint32_t*>(&h23));
        }
        {
            uint32_t off = (uint32_t)sn * LDA + sseg * 8;
            *reinterpret_cast<uint4*>(&sB[off]) = pb;
        }
        __syncthreads();

        if (c + 1 < 4) {
            int kn = kc + 32;
            #pragma unroll
            for (int i = 0; i < 4; i++) {
                int m = sm_ + i * 32, gr = m0 + m;
                pa[i]  = (gr < M) ? *reinterpret_cast<const float4*>(A   + (size_t)gr * 128 + kn + sc4 * 4)
                                  : make_float4(0.f, 0.f, 0.f, 0.f);
                pxo[i] = (gr < M) ? *reinterpret_cast<const float4*>(Xio + (size_t)gr * 128 + kn + sc4 * 4)
                                  : make_float4(0.f, 0.f, 0.f, 0.f);
            }
            pb = *reinterpret_cast<const uint4*>(W + (size_t)sn * 128 + kn + sseg * 8);
        }

        #pragma unroll
        for (int ks = 0; ks < 2; ks++) {
            uint32_t ko = ks * 32;
            uint32_t a4[2][4], b4[4][2];
            #pragma unroll
            for (int mt = 0; mt < 2; mt++) ldsm4(a4[mt], aA + mt * (16 * LDA * 2) + ko);
            #pragma unroll
            for (int p = 0; p < 2; p++)  ldsm4(&b4[p * 2][0], aB + p * (16 * LDA * 2) + ko);
            #pragma unroll
            for (int mt = 0; mt < 2; mt++)
                #pragma unroll
                for (int nt = 0; nt < 4; nt++) mma_fp16(acc[mt][nt], a4[mt], b4[nt]);
        }
        __syncthreads();
    }

    int mg = lane >> 2, cg = (lane & 3) * 2;
    #pragma unroll
    for (int mt = 0; mt < 2; mt++) {
        int r0 = m0 + wm * 32 + mt * 16 + mg;
        #pragma unroll
        for (int nt = 0; nt < 4; nt++) {
            int col = wn * 32 + nt * 8 + cg;
            if (col < NCLASS) {
                if (r0 < M)
                    *reinterpret_cast<__half2*>(C + (size_t)r0 * 40 + col) =
                        __floats2half2_rn(acc[mt][nt][0], acc[mt][nt][1]);
                if (r0 + 8 < M)
                    *reinterpret_cast<__half2*>(C + (size_t)(r0 + 8) * 40 + col) =
                        __floats2half2_rn(acc[mt][nt][2], acc[mt][nt][3]);
            }
        }
    }
}

// ---------------- CSR scans ----------------
__global__ void scan1_kernel() {
    __shared__ int s[512];
    int tid = threadIdx.x;
    int i = blockIdx.x * 512 + tid;
    int v = (i < N_NODES) ? g_cnt[i] : 0;
    s[tid] = v;
    __syncthreads();
    #pragma unroll
    for (int off = 1; off < 512; off <<= 1) {
        int t = (tid >= off) ? s[tid - off] : 0;
        __syncthreads();
        s[tid] += t;
        __syncthreads();
    }
    if (i < N_NODES) g_row_ptr[i] = s[tid] - v;
    if (tid == 511) g_bsum[blockIdx.x] = s[511];
}
// fused top-level scan + apply; also re-zeroes g_cnt for the next run
__global__ void scan23_kernel(int nb) {
    __shared__ int s[128];
    int tid = threadIdx.x;
    if (tid < 128) s[tid] = (tid < nb) ? g_bsum[tid] : 0;
    __syncthreads();
    #pragma unroll
    for (int off = 1; off < 128; off <<= 1) {
        int t = (tid < 128 && tid >= off) ? s[tid - off] : 0;
        __syncthreads();
        if (tid < 128) s[tid] += t;
        __syncthreads();
    }
    int base = s[blockIdx.x] - g_bsum[blockIdx.x];
    int i = blockIdx.x * 512 + tid;
    if (i < N_NODES) {
        int v = g_row_ptr[i] + base;
        g_row_ptr[i] = v;
        g_cursor[i]  = v;
        g_cnt[i]     = 0;        // ready for next run's histogram
    }
    if (i == 0) g_row_ptr[N_NODES] = N_EDGES;
}

// ---------------- SpMM (F=128, fp16 gather, unroll 8) + fused PairNorm stats -----
// stats_zero: previous layer's stats slab to clear (consumed already), or null.
__global__ void __launch_bounds__(256) spmm128_stats_kernel(
    const __half* __restrict__ h, float* __restrict__ out, float* __restrict__ stats,
    float* __restrict__ stats_zero) {
    __shared__ float s_col[128];
    __shared__ float s_ss;
    int tid = threadIdx.x;
    if (tid < 128) s_col[tid] = 0.f;
    if (tid == 0) s_ss = 0.f;
    if (stats_zero && blockIdx.x == 0 && tid < 129) stats_zero[tid] = 0.f;
    __syncthreads();

    int row  = (blockIdx.x * 256 + tid) >> 5;
    int lane = tid & 31;
    int s = g_row_ptr[row], e = g_row_ptr[row + 1];
    float4 acc = make_float4(0.f, 0.f, 0.f, 0.f);
    int i = s;
    for (; i + 8 <= e; i += 8) {
        int2 cv[8]; uint2 rr[8];
        #pragma unroll
        for (int u = 0; u < 8; u++) cv[u] = g_csr[i + u];
        #pragma unroll
        for (int u = 0; u < 8; u++)
            rr[u] = *reinterpret_cast<const uint2*>(h + (size_t)cv[u].x * 128 + lane * 4);
        #pragma unroll
        for (int u = 0; u < 8; u++) {
            float v = __int_as_float(cv[u].y);
            float2 a = __half22float2(*reinterpret_cast<__half2*>(&rr[u].x));
            float2 b = __half22float2(*reinterpret_cast<__half2*>(&rr[u].y));
            acc.x += v * a.x; acc.y += v * a.y; acc.z += v * b.x; acc.w += v * b.y;
        }
    }
    for (; i + 4 <= e; i += 4) {
        int2 cv[4]; uint2 rr[4];
        #pragma unroll
        for (int u = 0; u < 4; u++) cv[u] = g_csr[i + u];
        #pragma unroll
        for (int u = 0; u < 4; u++)
            rr[u] = *reinterpret_cast<const uint2*>(h + (size_t)cv[u].x * 128 + lane * 4);
        #pragma unroll
        for (int u = 0; u < 4; u++) {
            float v = __int_as_float(cv[u].y);
            float2 a = __half22float2(*reinterpret_cast<__half2*>(&rr[u].x));
            float2 b = __half22float2(*reinterpret_cast<__half2*>(&rr[u].y));
            acc.x += v * a.x; acc.y += v * a.y; acc.z += v * b.x; acc.w += v * b.y;
        }
    }
    for (; i < e; i++) {
        int2 cv = g_csr[i];
        float v = __int_as_float(cv.y);
        uint2 r = *reinterpret_cast<const uint2*>(h + (size_t)cv.x * 128 + lane * 4);
        float2 a = __half22float2(*reinterpret_cast<__half2*>(&r.x));
        float2 b = __half22float2(*reinterpret_cast<__half2*>(&r.y));
        acc.x += v * a.x; acc.y += v * a.y; acc.z += v * b.x; acc.w += v * b.y;
    }
    *reinterpret_cast<float4*>(out + (size_t)row * 128 + lane * 4) = acc;

    atomicAdd(&s_col[lane * 4 + 0], acc.x);
    atomicAdd(&s_col[lane * 4 + 1], acc.y);
    atomicAdd(&s_col[lane * 4 + 2], acc.z);
    atomicAdd(&s_col[lane * 4 + 3], acc.w);
    float ss = acc.x * acc.x + acc.y * acc.y + acc.z * acc.z + acc.w * acc.w;
    #pragma unroll
    for (int o = 16; o > 0; o >>= 1) ss += __shfl_xor_sync(0xFFFFFFFFu, ss, o);
    if (lane == 0) atomicAdd(&s_ss, ss);
    __syncthreads();
    if (tid < 128) atomicAdd(&stats[tid], s_col[tid]);
    if (tid == 128) atomicAdd(&stats[128], s_ss);
}

// ---------------- SpMM final (F=40 fp16, half-warp per row) + bias -> d_out ------
// Also zeroes st2 (read by the preceding head gemm) for the next run.
__global__ void spmm40_kernel(const __half* __restrict__ h,
                              const float* __restrict__ b_out,
                              float* __restrict__ out,
                              float* __restrict__ stats_zero) {
    if (blockIdx.x == 0 && threadIdx.x < 129) stats_zero[threadIdx.x] = 0.f;
    int hw = (blockIdx.x * blockDim.x + threadIdx.x) >> 4;
    if (hw >= N_NODES) return;
    int l = threadIdx.x & 15;
    if (l >= 10) return;
    float4 acc = *reinterpret_cast<const float4*>(b_out + l * 4);
    int s = g_row_ptr[hw], e = g_row_ptr[hw + 1];
    int i = s;
    for (; i + 4 <= e; i += 4) {
        int2 cv[4]; uint2 rr[4];
        #pragma unroll
        for (int u = 0; u < 4; u++) cv[u] = g_csr[i + u];
        #pragma unroll
        for (int u = 0; u < 4; u++)
            rr[u] = *reinterpret_cast<const uint2*>(h + (size_t)cv[u].x * 40 + l * 4);
        #pragma unroll
        for (int u = 0; u < 4; u++) {
            float v = __int_as_float(cv[u].y);
            float2 a = __half22float2(*reinterpret_cast<__half2*>(&rr[u].x));
            float2 b = __half22float2(*reinterpret_cast<__half2*>(&rr[u].y));
            acc.x += v * a.x; acc.y += v * a.y; acc.z += v * b.x; acc.w += v * b.y;
        }
    }
    for (; i < e; i++) {
        int2 cv = g_csr[i];
        float v = __int_as_float(cv.y);
        uint2 r = *reinterpret_cast<const uint2*>(h + (size_t)cv.x * 40 + l * 4);
        float2 a = __half22float2(*reinterpret_cast<__half2*>(&r.x));
        float2 b = __half22float2(*reinterpret_cast<__half2*>(&r.y));
        acc.x += v * a.x; acc.y += v * a.y; acc.z += v * b.x; acc.w += v * b.y;
    }
    *reinterpret_cast<float4*>(out + (size_t)hw * 40 + l * 4) = acc;
}

// ---------------- driver (11 launches) ----------------
extern "C" void kernel_launch(void* const* d_in, const int* in_sizes, int n_in,
                              void* d_out, int out_size) {
    const float* x      = (const float*)d_in[0];
    const int*   erow   = (const int*)  d_in[1];
    const int*   ecol   = (const int*)  d_in[2];
    const float* evalv  = (const float*)d_in[3];
    const float* W0     = (const float*)d_in[4];
    const float* W1     = (const float*)d_in[6];
    const float* W2     = (const float*)d_in[8];
    const float* W_out  = (const float*)d_in[10];
    const float* b_out  = (const float*)d_in[11];
    float* out = (float*)d_out;

    __half* h1  = nullptr; cudaGetSymbolAddress((void**)&h1,  g_h1);
    float*  agg = nullptr; cudaGetSymbolAddress((void**)&agg, g_agg);
    float*  xb  = nullptr; cudaGetSymbolAddress((void**)&xb,  g_x);
    float*  st  = nullptr; cudaGetSymbolAddress((void**)&st,  g_stats3);
    __half* wt  = nullptr; cudaGetSymbolAddress((void**)&wt,  g_wt);

    const int NB_SCAN = (N_NODES + 511) / 512;      // 98
    const int EB      = (N_EDGES + 255) / 256;      // 3125
    const int SPMM_B  = (N_NODES * 32) / 256;       // 6250

    // 1: W convert + edge histogram (g_cnt pre-zeroed by previous run / static init)
    prep_hist_kernel<<<EB, 256>>>(W0, W1, W2, W_out, erow);
    // 2-3: prefix scans (scan23 also re-zeroes g_cnt)
    scan1_kernel<<<NB_SCAN, 512>>>();
    scan23_kernel<<<NB_SCAN, 512>>>(NB_SCAN);
    // 4: layer-0 GEMM (independent of CSR) ∥ scatter
    gemm0_scatter_kernel<<<MB_GRID + EB, 256>>>(x, wt, h1, erow, ecol, evalv);
    // 5: spmm L0 -> agg + st0
    spmm128_stats_kernel<<<SPMM_B, 256>>>(h1, agg, st, nullptr);
    // 6-7: layer 1 (gemm reads st0; spmm L1 zeroes st0 afterward)
    gemm_fused_kernel<<<MB_GRID, 256>>>(agg, wt + 65536, h1, xb, st, N_NODES, NHID, 1 | 4);
    spmm128_stats_kernel<<<SPMM_B, 256>>>(h1, agg, st + 129, st);
    // 8-9: layer 2
    gemm_fused_kernel<<<MB_GRID, 256>>>(agg, wt + 81920, h1, xb, st + 129, N_NODES, NHID, 1 | 2 | 4);
    spmm128_stats_kernel<<<SPMM_B, 256>>>(h1, agg, st + 258, st + 129);
    // 10-11: head gemm (reads st2) + final spmm (zeroes st2)
    gemm_out_mma_kernel<<<MB_GRID, 256>>>(agg, wt + 98304, xb, st + 258, h1, N_NODES);
    spmm40_kernel<<<(N_NODES * 16 + 255) / 256, 256>>>(h1, b_out, out, st + 258);
}